// round 16
// baseline (speedup 1.0000x reference)
#include <cuda_runtime.h>
#include <stdint.h>

// SpikeFP64Divider: gate-level FP64 restoring divider on rows of 64 {0,1} floats.
// Integer replica of the exact circuit semantics (13-bit modular exponent math,
// subnormal inputs treated as normals, mantissa-round carry-out structurally 0).
//
// R16: two-kernel split to separate the HBM read stream from the write stream.
//  K1: load A,B (67MB read) -> ballot-pack -> divide -> store packed result
//      words to a 1MB static scratch (L2-resident).
//  K2: load packed words (L2 hit) -> expand -> store floats (33.5MB write).
// Pack/divide = R4's verified path; unpack = R14's verified STG.128 path.

__device__ uint64_t g_packed[131072];   // 1 MB static scratch (allowed)

// ---------------- K1: read + pack + divide ----------------
__global__ __launch_bounds__(256) void spike_pack_div_kernel(
    const float* __restrict__ A, const float* __restrict__ B)
{
    const unsigned FULL = 0xFFFFFFFFu;
    const int lane = threadIdx.x & 31;
    const int warp = threadIdx.x >> 5;

    // Each warp owns 32 consecutive rows = 2048 floats.
    const long long warpRow = ((long long)blockIdx.x * 8 + warp) * 32;
    const long long elemBase = warpRow * 64;
    const uint32_t* __restrict__ Au = reinterpret_cast<const uint32_t*>(A) + elemBase;
    const uint32_t* __restrict__ Bu = reinterpret_cast<const uint32_t*>(B) + elemBase;

    // ---- Pack: 64 half-rows per array; ballot k covers row k/2, half k&1 ----
    uint32_t capA_hi = 0u, capA_lo = 0u, capB_hi = 0u, capB_lo = 0u;
#pragma unroll
    for (int k0 = 0; k0 < 64; k0 += 8) {
        uint32_t va[8], vb[8];
#pragma unroll
        for (int j = 0; j < 8; j++) va[j] = Au[(k0 + j) * 32 + lane];
#pragma unroll
        for (int j = 0; j < 8; j++) vb[j] = Bu[(k0 + j) * 32 + lane];
#pragma unroll
        for (int j = 0; j < 8; j++) {
            const int k = k0 + j;
            const uint32_t ba = __ballot_sync(FULL, va[j] != 0u);
            if (lane == (k >> 1)) { if (k & 1) capA_lo = ba; else capA_hi = ba; }
            const uint32_t bb = __ballot_sync(FULL, vb[j] != 0u);
            if (lane == (k >> 1)) { if (k & 1) capB_lo = bb; else capB_hi = bb; }
        }
    }
    // col c at bit 63-c: ballot bit l = col (half*32 + l) -> reverse each word.
    const uint64_t wa = ((uint64_t)__brev(capA_hi) << 32) | (uint64_t)__brev(capA_lo);
    const uint64_t wb = ((uint64_t)__brev(capB_hi) << 32) | (uint64_t)__brev(capB_lo);

    // ---- Circuit replica (one row per lane) ----
    const uint64_t M52 = 0x000FFFFFFFFFFFFFull;
    const uint32_t s_out = (uint32_t)((wa ^ wb) >> 63);
    const uint32_t ea = (uint32_t)(wa >> 52) & 0x7FFu;
    const uint32_t eb = (uint32_t)(wb >> 52) & 0x7FFu;
    const uint64_t ma = wa & M52;
    const uint64_t mb = wb & M52;

    const bool a_zero = (ea == 0u)     && (ma == 0ull);
    const bool b_zero = (eb == 0u)     && (mb == 0ull);
    const bool a_inf  = (ea == 0x7FFu) && (ma == 0ull);
    const bool b_inf  = (eb == 0x7FFu) && (mb == 0ull);
    const bool a_nan  = (ea == 0x7FFu) && (ma != 0ull);
    const bool b_nan  = (eb == 0x7FFu) && (mb != 0ull);

    const bool r_nan  = a_nan || b_nan || (a_zero && b_zero) || (a_inf && b_inf);
    const bool r_inf  = (!a_zero && b_zero) || (a_inf && !b_inf);
    const bool r_zero = (a_zero && !b_zero) || (!a_inf && b_inf);

    // 13-bit modular exponent arithmetic, as the ripple circuits do.
    int exp13 = ((int)ea - (int)eb + 1023) & 8191;

    // ---- Exact Q = floor(a * 2^56 / d) via 2 base-2^28 digits ----
    const uint64_t a = (1ull << 53) | (ma << 1);
    const uint64_t d = (1ull << 53) | (mb << 1);
    const int64_t  ds = (int64_t)d;
    const double inv = 1.0 / (double)d;

    int64_t q1 = (int64_t)((double)a * 0x1p28 * inv);
    int64_t r1 = (int64_t)((a << 28) - (uint64_t)q1 * d);
    if (r1 < 0)   { q1--; r1 += ds; }
    if (r1 < 0)   { q1--; r1 += ds; }
    if (r1 >= ds) { q1++; r1 -= ds; }

    int64_t q2 = (int64_t)((double)r1 * 0x1p28 * inv);
    int64_t r2 = (int64_t)(((uint64_t)r1 << 28) - (uint64_t)q2 * d);
    if (r2 < 0)   { q2--; r2 += ds; }
    if (r2 < 0)   { q2--; r2 += ds; }
    if (r2 >= ds) { q2++; r2 -= ds; }

    const uint64_t Q = ((uint64_t)q1 << 28) + (uint64_t)q2;  // 57-bit quotient
    const bool remnz = (r2 != 0);

    // Normalize + guard/round/sticky (Q bit 56 = first quotient bit).
    const uint32_t q0 = (uint32_t)(Q >> 56) & 1u;
    uint64_t mant;
    uint32_t rnd;
    bool sticky;
    if (q0) {
        mant   = (Q >> 4) & M52;
        rnd    = (uint32_t)(Q >> 3) & 1u;
        sticky = ((Q & 7ull) != 0ull) || remnz;
    } else {
        mant   = (Q >> 3) & M52;
        rnd    = (uint32_t)(Q >> 2) & 1u;
        sticky = ((Q & 3ull) != 0ull) || remnz;
        exp13  = (exp13 - 1) & 8191;
    }

    // RNE; circuit's 53-bit incrementer carry-out is structurally 0:
    // mantissa overflow wraps to 0 WITHOUT exponent bump (mask only).
    const uint32_t lsb = (uint32_t)mant & 1u;
    const uint32_t rup = (rnd && (sticky || lsb)) ? 1u : 0u;
    mant = (mant + (uint64_t)rup) & M52;

    const uint32_t exp_field = (uint32_t)exp13 & 0x7FFu;
    const bool ovf = ((exp13 >> 11) & 3) != 0;
    const bool unf = (((exp13 >> 12) & 1) != 0) || (exp13 == 0);

    const uint64_t sbit = (uint64_t)s_out << 63;
    uint64_t out;
    if (r_nan)       out = sbit | (0x7FFull << 52) | (1ull << 51);
    else if (r_inf)  out = sbit | (0x7FFull << 52);
    else if (r_zero) out = sbit;
    else if (ovf)    out = sbit | (0x7FFull << 52);
    else if (unf)    out = sbit;
    else             out = sbit | ((uint64_t)exp_field << 52) | mant;

    // ---- Store packed result word (coalesced 8B/lane; 1 MB total) ----
    g_packed[warpRow + lane] = out;
}

// ---------------- K2: expand packed words -> floats ----------------
__global__ __launch_bounds__(256) void spike_expand_kernel(float* __restrict__ O)
{
    const unsigned FULL = 0xFFFFFFFFu;
    const int lane = threadIdx.x & 31;
    const int warp = threadIdx.x >> 5;

    const long long warpRow = ((long long)blockIdx.x * 8 + warp) * 32;
    const uint64_t out = g_packed[warpRow + lane];   // lane r owns row r

    // Unpack (R14-verified): shuffle hi/lo from owner lane, STG.128.
    // float4 i = k*32+lane: row 2k+(lane>>4), nibble lane&15 of that row.
    const uint32_t hi_o = (uint32_t)(out >> 32);   // cols  0..31 (col c at bit 31-c)
    const uint32_t lo_o = (uint32_t)out;           // cols 32..63
    float4* __restrict__ O4 = reinterpret_cast<float4*>(O + warpRow * 64);
    const int hsel = (lane >> 4) & 1;              // which row of the pair I store
    const bool use_lo = (lane & 8) != 0;           // my 4 cols live in lo word?
    const int nsh = 28 - 4 * (lane & 7);           // nibble shift within word
#pragma unroll
    for (int k = 0; k < 16; k++) {
        const int src = 2 * k + hsel;              // row index = owner lane
        const uint32_t wh = __shfl_sync(FULL, hi_o, src);
        const uint32_t wl = __shfl_sync(FULL, lo_o, src);
        const uint32_t word = use_lo ? wl : wh;
        const uint32_t nib = (word >> nsh) & 0xFu;
        float4 v;
        v.x = __uint_as_float((nib & 8u) ? 0x3F800000u : 0u);
        v.y = __uint_as_float((nib & 4u) ? 0x3F800000u : 0u);
        v.z = __uint_as_float((nib & 2u) ? 0x3F800000u : 0u);
        v.w = __uint_as_float((nib & 1u) ? 0x3F800000u : 0u);
        O4[k * 32 + lane] = v;
    }
}

extern "C" void kernel_launch(void* const* d_in, const int* in_sizes, int n_in,
                              void* d_out, int out_size) {
    const float* A = (const float*)d_in[0];
    const float* B = (const float*)d_in[1];
    float* O = (float*)d_out;
    const int rows = in_sizes[0] / 64;       // 131072
    const int grid = rows / 256;             // 512 blocks, 8 warps x 32 rows
    spike_pack_div_kernel<<<grid, 256>>>(A, B);
    spike_expand_kernel<<<grid, 256>>>(O);
}